// round 3
// baseline (speedup 1.0000x reference)
#include <cuda_runtime.h>

#define N_ROWS 16384
#define D      2048
#define ETA    0.01f
#define GRID1  592          // 4 CTAs per SM on 148 SMs
#define THREADS 256
#define RPB    4            // rows per batch per CTA
#define STRIDE (GRID1 * RPB)   // 2368 rows per sweep
#define NGRP   16           // 592 = 16 * 37

// Scratch: per-CTA partial accumulation of sum_k c_k * x_k  (4.85 MB)
__device__ float g_partial[GRID1][D];
// Stage-2 scratch: 16 group partials (128 KB)
__device__ float g_stage[NGRP][D];

__global__ __launch_bounds__(THREADS, 4)
void pass1_kernel(const float* __restrict__ theta,
                  const float* __restrict__ xs)
{
    __shared__ float s_dot[8][RPB];   // [warp][row-in-batch]
    __shared__ float s_c[RPB];

    const int t = threadIdx.x;
    const int wid = t >> 5;
    const int lane = t & 31;

    // Each thread owns columns [4t,4t+4) and [1024+4t,1024+4t+4)
    const float4 th0 = *reinterpret_cast<const float4*>(theta + 4 * t);
    const float4 th1 = *reinterpret_cast<const float4*>(theta + 1024 + 4 * t);

    float4 acc0 = make_float4(0.f, 0.f, 0.f, 0.f);
    float4 acc1 = make_float4(0.f, 0.f, 0.f, 0.f);

    // 7 sweeps cover 16384 rows (7 * 2368 = 16576)
    for (int base = blockIdx.x * RPB; base < N_ROWS; base += STRIDE) {
        float4 a[RPB][2];

        // Issue all 8 float4 loads (32 KB contiguous per CTA) before any use.
        #pragma unroll
        for (int j = 0; j < RPB; j++) {
            const int rj = base + j;
            if (rj < N_ROWS) {
                const float* row = xs + (size_t)rj * D;
                a[j][0] = *reinterpret_cast<const float4*>(row + 4 * t);
                a[j][1] = *reinterpret_cast<const float4*>(row + 1024 + 4 * t);
            } else {
                a[j][0] = make_float4(0.f, 0.f, 0.f, 0.f);
                a[j][1] = make_float4(0.f, 0.f, 0.f, 0.f);
            }
        }

        // 4 partial dots, 4 concurrent warp reductions
        float s[RPB];
        #pragma unroll
        for (int j = 0; j < RPB; j++) {
            s[j] = a[j][0].x * th0.x + a[j][0].y * th0.y
                 + a[j][0].z * th0.z + a[j][0].w * th0.w
                 + a[j][1].x * th1.x + a[j][1].y * th1.y
                 + a[j][1].z * th1.z + a[j][1].w * th1.w;
        }
        #pragma unroll
        for (int o = 16; o > 0; o >>= 1) {
            #pragma unroll
            for (int j = 0; j < RPB; j++)
                s[j] += __shfl_down_sync(0xffffffffu, s[j], o);
        }
        if (lane == 0) {
            #pragma unroll
            for (int j = 0; j < RPB; j++)
                s_dot[wid][j] = s[j];
        }
        __syncthreads();

        if (t < RPB) {
            float p = s_dot[0][t];
            #pragma unroll
            for (int w = 1; w < 8; w++) p += s_dot[w][t];
            s_c[t] = ETA / (1.0f + __expf(p));
            // invalid (zero-filled) rows: a==0 so c*a contributes 0 regardless
        }
        __syncthreads();

        #pragma unroll
        for (int j = 0; j < RPB; j++) {
            const float c = s_c[j];
            acc0.x += c * a[j][0].x;  acc0.y += c * a[j][0].y;
            acc0.z += c * a[j][0].z;  acc0.w += c * a[j][0].w;
            acc1.x += c * a[j][1].x;  acc1.y += c * a[j][1].y;
            acc1.z += c * a[j][1].z;  acc1.w += c * a[j][1].w;
        }
        __syncthreads();   // protect s_dot/s_c reuse next sweep
    }

    float* part = g_partial[blockIdx.x];
    *reinterpret_cast<float4*>(part + 4 * t)        = acc0;
    *reinterpret_cast<float4*>(part + 1024 + 4 * t) = acc1;
}

// Stage A: 592 partials -> 16 group partials, float4 lanes.
// grid (4, 16), 128 threads: col4 = bx*128+tid (0..511), group by sums 37 rows.
__global__ __launch_bounds__(128)
void pass2a_kernel()
{
    const int col4 = blockIdx.x * 128 + threadIdx.x;
    const int g    = blockIdx.y;

    float4 s = make_float4(0.f, 0.f, 0.f, 0.f);
    const int b0 = g * 37;
    #pragma unroll
    for (int b = b0; b < b0 + 37; b++) {
        const float4 v = reinterpret_cast<const float4*>(g_partial[b])[col4];
        s.x += v.x; s.y += v.y; s.z += v.z; s.w += v.w;
    }
    reinterpret_cast<float4*>(g_stage[g])[col4] = s;
}

// Stage B: fold 16 group partials + theta0 -> out. 512 threads, float4.
__global__ __launch_bounds__(128)
void pass2b_kernel(const float* __restrict__ theta,
                   float* __restrict__ out)
{
    const int col4 = blockIdx.x * 128 + threadIdx.x;
    float4 s = reinterpret_cast<const float4*>(theta)[col4];
    #pragma unroll
    for (int g = 0; g < NGRP; g++) {
        const float4 v = reinterpret_cast<const float4*>(g_stage[g])[col4];
        s.x += v.x; s.y += v.y; s.z += v.z; s.w += v.w;
    }
    reinterpret_cast<float4*>(out)[col4] = s;
}

extern "C" void kernel_launch(void* const* d_in, const int* in_sizes, int n_in,
                              void* d_out, int out_size)
{
    const float* theta = (const float*)d_in[0];
    const float* xs    = (const float*)d_in[1];
    if (n_in >= 2 && in_sizes[0] > in_sizes[1]) {   // guard against input-order surprise
        theta = (const float*)d_in[1];
        xs    = (const float*)d_in[0];
    }
    float* out = (float*)d_out;

    pass1_kernel<<<GRID1, THREADS>>>(theta, xs);
    pass2a_kernel<<<dim3(4, NGRP), 128>>>();
    pass2b_kernel<<<4, 128>>>(theta, out);
}

// round 4
// speedup vs baseline: 1.2062x; 1.2062x over previous
#include <cuda_runtime.h>

#define N_ROWS  16384
#define D       2048
#define ETA     0.01f
#define GRID1   148
#define THREADS 256
#define RPS     8                   // rows per pipeline stage
#define NSTAGE  3
#define SWEEP   (GRID1 * RPS)       // 1184 rows per sweep
#define STAGE_FLOATS (RPS * D)      // 16384 floats = 64 KB

// Per-CTA partials: 148 x 2048 floats (1.2 MB)
__device__ float g_partial[GRID1][D];

__device__ __forceinline__ void cp_async16(float* smem_dst, const float* gsrc) {
    unsigned s = (unsigned)__cvta_generic_to_shared(smem_dst);
    asm volatile("cp.async.cg.shared.global [%0], [%1], 16;\n" :: "r"(s), "l"(gsrc));
}
__device__ __forceinline__ void cp_commit() {
    asm volatile("cp.async.commit_group;\n");
}
template <int N>
__device__ __forceinline__ void cp_wait() {
    asm volatile("cp.async.wait_group %0;\n" :: "n"(N));
}

__global__ __launch_bounds__(THREADS, 1)
void pass1_kernel(const float* __restrict__ theta,
                  const float* __restrict__ xs)
{
    extern __shared__ float buf[];        // NSTAGE * RPS * D floats (192 KB)
    __shared__ float s_dot[8][RPS];
    __shared__ float s_c[RPS];

    const int t    = threadIdx.x;
    const int wid  = t >> 5;
    const int lane = t & 31;

    // Thread t owns columns [4t,4t+4) and [1024+4t,1024+4t+4)
    const float4 th0 = *reinterpret_cast<const float4*>(theta + 4 * t);
    const float4 th1 = *reinterpret_cast<const float4*>(theta + 1024 + 4 * t);

    float4 acc0 = make_float4(0.f, 0.f, 0.f, 0.f);
    float4 acc1 = make_float4(0.f, 0.f, 0.f, 0.f);

    const int first = blockIdx.x * RPS;
    const int nst   = (N_ROWS - first + SWEEP - 1) / SWEEP;   // 13 or 14

    // ---- stage issue: 16 cp.asyncs per thread (64 KB per stage per CTA) ----
    auto issue = [&](int s) {
        float* dst = buf + (s % NSTAGE) * STAGE_FLOATS;
        const int base = first + s * SWEEP;
        #pragma unroll
        for (int j = 0; j < RPS; j++) {
            int rj = base + j;
            if (rj > N_ROWS - 1) rj = N_ROWS - 1;   // clamp; c forced to 0 later
            const float* row = xs + (size_t)rj * D;
            cp_async16(dst + j * D + 4 * t,        row + 4 * t);
            cp_async16(dst + j * D + 1024 + 4 * t, row + 1024 + 4 * t);
        }
    };

    // prologue: stages 0..NSTAGE-2 (one commit group per stage, even if empty)
    #pragma unroll
    for (int s = 0; s < NSTAGE - 1; s++) {
        if (s < nst) issue(s);
        cp_commit();
    }

    for (int s = 0; s < nst; s++) {
        const int sn = s + NSTAGE - 1;
        if (sn < nst) issue(sn);
        cp_commit();
        cp_wait<NSTAGE - 1>();        // stage s has landed
        __syncthreads();

        const float* src = buf + (s % NSTAGE) * STAGE_FLOATS;
        float4 a[RPS][2];
        float  sm[RPS];

        #pragma unroll
        for (int j = 0; j < RPS; j++) {
            a[j][0] = *reinterpret_cast<const float4*>(src + j * D + 4 * t);
            a[j][1] = *reinterpret_cast<const float4*>(src + j * D + 1024 + 4 * t);
            sm[j] = a[j][0].x * th0.x + a[j][0].y * th0.y
                  + a[j][0].z * th0.z + a[j][0].w * th0.w
                  + a[j][1].x * th1.x + a[j][1].y * th1.y
                  + a[j][1].z * th1.z + a[j][1].w * th1.w;
        }

        // 8 concurrent warp reductions
        #pragma unroll
        for (int o = 16; o > 0; o >>= 1) {
            #pragma unroll
            for (int j = 0; j < RPS; j++)
                sm[j] += __shfl_down_sync(0xffffffffu, sm[j], o);
        }
        if (lane == 0) {
            #pragma unroll
            for (int j = 0; j < RPS; j++)
                s_dot[wid][j] = sm[j];
        }
        __syncthreads();

        if (t < RPS) {
            float p = s_dot[0][t];
            #pragma unroll
            for (int w = 1; w < 8; w++) p += s_dot[w][t];
            const int rj = first + s * SWEEP + t;
            s_c[t] = (rj < N_ROWS) ? (ETA / (1.0f + __expf(p))) : 0.f;
        }
        __syncthreads();   // also guarantees all LDS of buf[s] done before reuse

        #pragma unroll
        for (int j = 0; j < RPS; j++) {
            const float c = s_c[j];
            acc0.x += c * a[j][0].x;  acc0.y += c * a[j][0].y;
            acc0.z += c * a[j][0].z;  acc0.w += c * a[j][0].w;
            acc1.x += c * a[j][1].x;  acc1.y += c * a[j][1].y;
            acc1.z += c * a[j][1].z;  acc1.w += c * a[j][1].w;
        }
    }

    float* part = g_partial[blockIdx.x];
    *reinterpret_cast<float4*>(part + 4 * t)        = acc0;
    *reinterpret_cast<float4*>(part + 1024 + 4 * t) = acc1;
}

// Single reduction kernel: 148 partials + theta -> out.
// grid 32 x 256: thread = (col4 = bid*16 + t>>4, g = t&15); each sums
// partial rows g, g+16, ... ; combine the 16 groups with warp shuffles.
__global__ __launch_bounds__(THREADS)
void pass2_kernel(const float* __restrict__ theta,
                  float* __restrict__ out)
{
    const int g    = threadIdx.x & 15;
    const int col4 = blockIdx.x * 16 + (threadIdx.x >> 4);

    float4 s = make_float4(0.f, 0.f, 0.f, 0.f);
    for (int b = g; b < GRID1; b += 16) {
        const float4 v = reinterpret_cast<const float4*>(g_partial[b])[col4];
        s.x += v.x; s.y += v.y; s.z += v.z; s.w += v.w;
    }

    // reduce over g (low 4 lane bits, stays within warp halves)
    #pragma unroll
    for (int o = 8; o > 0; o >>= 1) {
        s.x += __shfl_xor_sync(0xffffffffu, s.x, o);
        s.y += __shfl_xor_sync(0xffffffffu, s.y, o);
        s.z += __shfl_xor_sync(0xffffffffu, s.z, o);
        s.w += __shfl_xor_sync(0xffffffffu, s.w, o);
    }

    if (g == 0) {
        const float4 th = reinterpret_cast<const float4*>(theta)[col4];
        float4 r;
        r.x = th.x + s.x; r.y = th.y + s.y;
        r.z = th.z + s.z; r.w = th.w + s.w;
        reinterpret_cast<float4*>(out)[col4] = r;
    }
}

extern "C" void kernel_launch(void* const* d_in, const int* in_sizes, int n_in,
                              void* d_out, int out_size)
{
    const float* theta = (const float*)d_in[0];
    const float* xs    = (const float*)d_in[1];
    if (n_in >= 2 && in_sizes[0] > in_sizes[1]) {   // guard against input-order surprise
        theta = (const float*)d_in[1];
        xs    = (const float*)d_in[0];
    }
    float* out = (float*)d_out;

    const int smem = NSTAGE * STAGE_FLOATS * sizeof(float);   // 196608
    cudaFuncSetAttribute(pass1_kernel,
                         cudaFuncAttributeMaxDynamicSharedMemorySize, smem);

    pass1_kernel<<<GRID1, THREADS, smem>>>(theta, xs);
    pass2_kernel<<<32, THREADS>>>(theta, out);
}